// round 4
// baseline (speedup 1.0000x reference)
#include <cuda_runtime.h>

// ---------------------------------------------------------------------------
// QuantSoftmax (I-BERT int softmax) for x: (2,12,1024,1024) fp32, row = 1024.
//
// Kernel 1: global abs-max (grid partials + last-block-finishes reduction),
//           derives all loop-invariant scalars, writes out_scale tail.
// Kernel 2: 4 warps per row (8 elems/lane in regs) -> low reg pressure,
//           high occupancy. Two __syncthreads per block (block = 2 rows).
// ---------------------------------------------------------------------------

#define ROWLEN 1024
#define K1_BLOCKS 1024
#define K1_THREADS 256

static __device__ float g_part[K1_BLOCKS];
static __device__ unsigned g_count = 0;

struct QParams {
    float s;       // scaling_factor
    float ys;      // rn(1/s)
    float x0i;     // floor(-0.6931 / s)
    float yx0;     // rn(1/x0i)
    float bi;      // floor(COEF_B / s)
    float ci;      // floor(COEF_C / s^2)
    float exp_sf;  // (COEF_A * s^2) / 2^30
    float scale2;  // inner QuantAct scale (analytic global max of exp_real)
    float ys2;     // rn(1/scale2)
    float t30x0;   // 30 * x0i
};
static __device__ QParams g_p;

// Correctly-rounded a/b given y = __frcp_rn(b)  (Markstein refinement).
__device__ __forceinline__ float fdivrn(float a, float b, float y) {
    float q0 = __fmul_rn(a, y);
    float r0 = __fmaf_rn(-b, q0, a);
    return __fmaf_rn(r0, y, q0);
}

// ------------- Kernel 1: abs-max + params + tail (single kernel) -----------
__global__ void __launch_bounds__(K1_THREADS) k_absmax(const float4* __restrict__ x, int n4,
                                                       float* __restrict__ out,
                                                       int n, int out_size) {
    // 4 independent accumulators for MLP
    float m0 = 0.0f, m1 = 0.0f, m2 = 0.0f, m3 = 0.0f;
    int tid = blockIdx.x * blockDim.x + threadIdx.x;
    int stride = gridDim.x * blockDim.x;
    int i = tid;
    for (; i + 3 * stride < n4; i += 4 * stride) {
        float4 a = x[i];
        float4 b = x[i + stride];
        float4 c = x[i + 2 * stride];
        float4 d = x[i + 3 * stride];
        m0 = fmaxf(m0, fmaxf(fmaxf(fabsf(a.x), fabsf(a.y)), fmaxf(fabsf(a.z), fabsf(a.w))));
        m1 = fmaxf(m1, fmaxf(fmaxf(fabsf(b.x), fabsf(b.y)), fmaxf(fabsf(b.z), fabsf(b.w))));
        m2 = fmaxf(m2, fmaxf(fmaxf(fabsf(c.x), fabsf(c.y)), fmaxf(fabsf(c.z), fabsf(c.w))));
        m3 = fmaxf(m3, fmaxf(fmaxf(fabsf(d.x), fabsf(d.y)), fmaxf(fabsf(d.z), fabsf(d.w))));
    }
    for (; i < n4; i += stride) {
        float4 a = x[i];
        m0 = fmaxf(m0, fmaxf(fmaxf(fabsf(a.x), fabsf(a.y)), fmaxf(fabsf(a.z), fabsf(a.w))));
    }
    float m = fmaxf(fmaxf(m0, m1), fmaxf(m2, m3));
#pragma unroll
    for (int o = 16; o > 0; o >>= 1)
        m = fmaxf(m, __shfl_xor_sync(0xffffffffu, m, o));
    __shared__ float sm[K1_THREADS / 32];
    __shared__ bool amLast;
    if ((threadIdx.x & 31) == 0) sm[threadIdx.x >> 5] = m;
    __syncthreads();
    if (threadIdx.x == 0) {
#pragma unroll
        for (int k = 1; k < K1_THREADS / 32; k++) m = fmaxf(m, sm[k]);
        g_part[blockIdx.x] = m;
        __threadfence();
        unsigned prev = atomicAdd(&g_count, 1u);
        amLast = (prev == gridDim.x - 1);
    }
    __syncthreads();
    if (!amLast) return;

    // ---- last block: finish reduction over 1024 partials ----
    float mm = 0.0f;
#pragma unroll
    for (int k = 0; k < K1_BLOCKS / K1_THREADS; k++)
        mm = fmaxf(mm, __ldcg(&g_part[threadIdx.x + k * K1_THREADS]));
#pragma unroll
    for (int o = 16; o > 0; o >>= 1)
        mm = fmaxf(mm, __shfl_xor_sync(0xffffffffu, mm, o));
    if ((threadIdx.x & 31) == 0) sm[threadIdx.x >> 5] = mm;
    __syncthreads();

    // out_scale tail elements (usually 1 scalar)
    for (int t = n + threadIdx.x; t < out_size; t += K1_THREADS)
        out[t] = 0.00390625f;  // 1 / 2^8

    if (threadIdx.x == 0) {
        mm = sm[0];
#pragma unroll
        for (int k = 1; k < K1_THREADS / 32; k++) mm = fmaxf(mm, sm[k]);

        const float CA  = (float)(0.35815147);
        const float CB  = (float)(0.96963238 / 0.35815147);
        const float CC  = (float)(1.0 / 0.35815147);
        const float X0F = (float)(-0.6931);

        float s   = __fdiv_rn(mm, 32767.0f);
        float x0i = floorf(__fdiv_rn(X0F, s));
        float bi  = floorf(__fdiv_rn(CB, s));
        float s2  = __fmul_rn(s, s);
        float ci  = floorf(__fdiv_rn(CC, s2));
        float exp_sf = __fmul_rn(__fmul_rn(CA, s2), 9.31322574615478516e-10f /* 2^-30 */);
        // Global max of exp_real (attained at every row max):
        float ermax  = __fmul_rn(__fmul_rn(ci, 1073741824.0f), exp_sf);
        float scale2 = __fdiv_rn(ermax, 32767.0f);

        QParams p;
        p.s = s;          p.ys  = __frcp_rn(s);
        p.x0i = x0i;      p.yx0 = __frcp_rn(x0i);
        p.bi = bi;        p.ci  = ci;
        p.exp_sf = exp_sf;
        p.scale2 = scale2; p.ys2 = __frcp_rn(scale2);
        p.t30x0 = __fmul_rn(30.0f, x0i);
        g_p = p;
        g_count = 0;  // reset for next graph replay
    }
}

// ------------- Kernel 2: 4-warps-per-row int softmax ------------------------
// block = 256 threads = 8 warps = 2 rows. 8 elems (2 float4) per lane.
__global__ void __launch_bounds__(256, 4) k_softmax(const float* __restrict__ x,
                                                    float* __restrict__ out) {
    __shared__ float s_max[8];
    __shared__ int   s_k[8];
    __shared__ float s_d[8];

    const QParams p = g_p;

    const unsigned w   = threadIdx.x >> 5;          // warp in block (0..7)
    const unsigned r   = w >> 2;                    // row in block (0..1)
    const unsigned t   = threadIdx.x & 127u;        // thread in row (0..127)
    const size_t row = (size_t)blockIdx.x * 2 + r;

    const float4* xr = reinterpret_cast<const float4*>(x + row * ROWLEN);
    float4* orow = reinterpret_cast<float4*>(out + row * ROWLEN);

    // --- load 8 elems/lane: two coalesced float4 per thread ---
    float4 va = xr[t];
    float4 vb = xr[t + 128];
    float pay[8] = {va.x, va.y, va.z, va.w, vb.x, vb.y, vb.z, vb.w};

    // --- quantize + dequantized integer representation (in place); max ---
    // Clamps are provably dead: |x| <= max|x| => |x/s| <= 32767*(1+2^-23) < 32767.5
    float lmax = -3.0e38f;
#pragma unroll
    for (int j = 0; j < 8; j++) {
        float xi = rintf(fdivrn(pay[j], p.s, p.ys));
        float qx = __fmul_rn(xi, p.s);
        float xii = fdivrn(qx, p.s, p.ys);
        pay[j] = xii;
        lmax = fmaxf(lmax, xii);
    }

    // --- row max: warp shfl + cross-warp via smem (one barrier) ---
#pragma unroll
    for (int o = 16; o > 0; o >>= 1)
        lmax = fmaxf(lmax, __shfl_xor_sync(0xffffffffu, lmax, o));
    if ((threadIdx.x & 31) == 0) s_max[w] = lmax;
    __syncthreads();
    float rmax = fmaxf(fmaxf(s_max[r * 4 + 0], s_max[r * 4 + 1]),
                       fmaxf(s_max[r * 4 + 2], s_max[r * 4 + 3]));

    // --- int exp + inner requant (in place); exact sum (int + residual) ---
    int   ksum = 0;
    float dsum = 0.0f;
#pragma unroll
    for (int j = 0; j < 8; j++) {
        float tt = __fsub_rn(pay[j], rmax);
        tt = fmaxf(tt, p.t30x0);
        float q = floorf(fdivrn(tt, p.x0i, p.yx0));
        float rr = __fsub_rn(tt, __fmul_rn(p.x0i, q));
        float z = __fadd_rn(__fmul_rn(rr, __fadd_rn(rr, p.bi)), p.ci);
        // 2^(30-q): q integer-valued in [0,30] -> exact bit construction
        int e = (int)__fsub_rn(30.0f, q);
        float p2 = __int_as_float((e + 127) << 23);
        float ei = fmaxf(floorf(__fmul_rn(z, p2)), 0.0f);
        float er = __fmul_rn(ei, p.exp_sf);
        // kf in [0, 32767]: clamp dead (er <= ermax, scale2 = ermax/32767)
        float kf = rintf(fdivrn(er, p.scale2, p.ys2));
        float erq = __fmul_rn(kf, p.scale2);
        float ee = fdivrn(erq, p.scale2, p.ys2);
        pay[j] = ee;
        ksum += (int)kf;
        dsum = __fadd_rn(dsum, __fsub_rn(ee, kf));  // exact residual (Sterbenz)
    }

    // --- row sum: warp redux/shfl + cross-warp via smem (one barrier) ---
    ksum = __reduce_add_sync(0xffffffffu, ksum);
#pragma unroll
    for (int o = 16; o > 0; o >>= 1)
        dsum = __fadd_rn(dsum, __shfl_xor_sync(0xffffffffu, dsum, o));
    if ((threadIdx.x & 31) == 0) { s_k[w] = ksum; s_d[w] = dsum; }
    __syncthreads();
    int   K = ((s_k[r * 4 + 0] + s_k[r * 4 + 1]) + s_k[r * 4 + 2]) + s_k[r * 4 + 3];
    float D = __fadd_rn(__fadd_rn(__fadd_rn(s_d[r * 4 + 0], s_d[r * 4 + 1]),
                                  s_d[r * 4 + 2]), s_d[r * 4 + 3]);

    // every thread computes factor (deterministic, identical per row)
    float sumf = (float)((double)K + (double)D);  // correctly-rounded row sum
    float ysf = __frcp_rn(sumf);
    float factor = floorf(fdivrn(4294967296.0f, sumf, ysf));
    // factor * 2^-24: exact power-of-2 scale, commutes with fp32 rounding
    float f24 = __fmul_rn(factor, 5.96046447753906250e-08f);

    // --- output: floor(e2 * factor / 2^24) * (1/256), streaming stores ---
    float4 oa, ob;
    oa.x = __fmul_rn(floorf(__fmul_rn(pay[0], f24)), 0.00390625f);
    oa.y = __fmul_rn(floorf(__fmul_rn(pay[1], f24)), 0.00390625f);
    oa.z = __fmul_rn(floorf(__fmul_rn(pay[2], f24)), 0.00390625f);
    oa.w = __fmul_rn(floorf(__fmul_rn(pay[3], f24)), 0.00390625f);
    ob.x = __fmul_rn(floorf(__fmul_rn(pay[4], f24)), 0.00390625f);
    ob.y = __fmul_rn(floorf(__fmul_rn(pay[5], f24)), 0.00390625f);
    ob.z = __fmul_rn(floorf(__fmul_rn(pay[6], f24)), 0.00390625f);
    ob.w = __fmul_rn(floorf(__fmul_rn(pay[7], f24)), 0.00390625f);
    __stcs(orow + t, oa);
    __stcs(orow + t + 128, ob);
}

extern "C" void kernel_launch(void* const* d_in, const int* in_sizes, int n_in,
                              void* d_out, int out_size) {
    const float* x = (const float*)d_in[0];
    float* out = (float*)d_out;
    int n = in_sizes[0];
    int n4 = n / 4;

    k_absmax<<<K1_BLOCKS, K1_THREADS>>>((const float4*)x, n4, out, n, out_size);

    int rows = n / ROWLEN;           // 24576 rows, 2 rows per block
    k_softmax<<<rows / 2, 256>>>(x, out);
}